// round 16
// baseline (speedup 1.0000x reference)
#include <cuda_runtime.h>
#include <math.h>

#define Nn 50000
#define Ee 500000
#define Dd 16
#define EFf 8
#define Cc 10
#define Gg 500
#define BN_EPS 1e-5f
#define NBS 196   // ceil(Nn/256)

// ---------------- device scratch (static, allocation-free) ----------------
__device__ float  g_he[(size_t)Ee * Dd];     // per-edge MLP hidden, dst-sorted order
__device__ float  g_h[Nn * Dd];              // current node features
__device__ float  g_h2[Nn * Dd];             // pre-BN features
__device__ int    g_cnt[Nn];                 // histogram
__device__ int    g_rank[Ee];                // per-edge rank within its dst bucket
__device__ int    g_eoff[Nn + 1];            // CSR offsets (edges sorted by dst)
__device__ int    g_bsum[256];               // scan block sums
__device__ int    g_srcs[Ee];                // src id, dst-sorted order
__device__ double g_stat3[3 * 32];           // per-layer BN sum/sumsq slots
__device__ float  g_pooled[Gg * 4 * Dd];     // pooled scratch (fallback path)
__device__ float  g_fcbuf[Gg * Cc];          // fc scratch (fallback path)

// fast tanh: 1 - 2/(e^{2x}+1); exact at +/-inf, ~1e-6 rel err
__device__ __forceinline__ float ftanh(float x) {
    float e = __expf(2.0f * x);
    return 1.0f - __fdividef(2.0f, e + 1.0f);
}

// ---------------- setup kernels ----------------

__global__ void k_setup(const float* __restrict__ x) {
    int i = blockIdx.x * blockDim.x + threadIdx.x;
    if (i < Nn * Dd) g_h[i] = x[i];
    if (i < Nn) g_cnt[i] = 0;
    if (i < 3 * 32) g_stat3[i] = 0.0;
}

__global__ void k_hist(const int* __restrict__ dst) {
    int e = blockIdx.x * blockDim.x + threadIdx.x;
    if (e < Ee) g_rank[e] = atomicAdd(&g_cnt[dst[e]], 1);
}

__global__ void k_scanA() {
    __shared__ int sh[256];
    int t = threadIdx.x;
    int i = blockIdx.x * 256 + t;
    int v = (i < Nn) ? g_cnt[i] : 0;
    sh[t] = v; __syncthreads();
    for (int ofs = 1; ofs < 256; ofs <<= 1) {
        int add = (t >= ofs) ? sh[t - ofs] : 0;
        __syncthreads();
        sh[t] += add;
        __syncthreads();
    }
    if (i < Nn) g_eoff[i] = sh[t] - v;         // exclusive
    if (t == 255) g_bsum[blockIdx.x] = sh[255];
}

__global__ void k_scanB() {
    __shared__ int sh[256];
    int t = threadIdx.x;
    int v = (t < NBS) ? g_bsum[t] : 0;
    sh[t] = v; __syncthreads();
    for (int ofs = 1; ofs < 256; ofs <<= 1) {
        int add = (t >= ofs) ? sh[t - ofs] : 0;
        __syncthreads();
        sh[t] += add;
        __syncthreads();
    }
    if (t < NBS) g_bsum[t] = sh[t] - v;        // exclusive
}

__global__ void k_scanC() {
    int i = blockIdx.x * blockDim.x + threadIdx.x;
    if (i < Nn) g_eoff[i] += g_bsum[i >> 8];
    if (i == 0) g_eoff[Nn] = Ee;
}

// fused: scatter src into sorted order + compute edge MLP row directly into
// the sorted slot. edge_attr read COALESCED (thread e = edge e).
__global__ void k_scatter_mlp(const int* __restrict__ src, const int* __restrict__ dst,
                              const float* __restrict__ ea,
                              const float* __restrict__ w1, const float* __restrict__ b1) {
    __shared__ float sw1t[16][8];   // [c][f]
    __shared__ float sb1[16];
    if (threadIdx.x < 128) {
        int f = threadIdx.x >> 4, c = threadIdx.x & 15;
        sw1t[c][f] = w1[threadIdx.x];
    }
    if (threadIdx.x < 16) sb1[threadIdx.x] = b1[threadIdx.x];
    __syncthreads();
    int e = blockIdx.x * blockDim.x + threadIdx.x;
    if (e >= Ee) return;
    int d = dst[e];
    int pos = g_eoff[d] + g_rank[e];
    g_srcs[pos] = src[e];
    float4 a0 = *(const float4*)(ea + (size_t)e * 8);
    float4 a1 = *(const float4*)(ea + (size_t)e * 8 + 4);
    float hv[16];
#pragma unroll
    for (int c = 0; c < 16; c++) {
        const float* wc = sw1t[c];
        float acc = sb1[c];
        acc = fmaf(a0.x, wc[0], acc); acc = fmaf(a0.y, wc[1], acc);
        acc = fmaf(a0.z, wc[2], acc); acc = fmaf(a0.w, wc[3], acc);
        acc = fmaf(a1.x, wc[4], acc); acc = fmaf(a1.y, wc[5], acc);
        acc = fmaf(a1.z, wc[6], acc); acc = fmaf(a1.w, wc[7], acc);
        hv[c] = ftanh(acc);
    }
    float4* hp = (float4*)(g_he + (size_t)pos * 16);
    hp[0] = make_float4(hv[0],  hv[1],  hv[2],  hv[3]);
    hp[1] = make_float4(hv[4],  hv[5],  hv[6],  hv[7]);
    hp[2] = make_float4(hv[8],  hv[9],  hv[10], hv[11]);
    hp[3] = make_float4(hv[12], hv[13], hv[14], hv[15]);
}

// ---------------- fused NNConv layer: 2 nodes per warp ----------------
// S[j,i] = sum_e he[e,j]*h[src,i], T[i] = sum_e h[src,i]; contraction against
// transposed+padded w2t[o][row] amortized across the node pair.
__global__ void k_conv(const float* __restrict__ w2g, const float* __restrict__ b2g,
                       const float* __restrict__ rootg, const float* __restrict__ biasg,
                       int layer) {
    __shared__ float sw2t[16 * 264];     // [o][row=j*16+i], pitch 264
    __shared__ float sb2t[16 * 20];      // [o][i], pitch 20
    __shared__ float sroot[256];         // [i*16+o]
    __shared__ float sbias[16];
    __shared__ float sS[8][544];         // per warp: node0 S[256]+T[16], node1 at +272
    __shared__ float bsum[16], bsq[16];

    for (int t = threadIdx.x; t < 4096; t += 256) {
        int row = t >> 4, o = t & 15;
        sw2t[o * 264 + row] = w2g[t];
    }
    if (threadIdx.x < 256) {
        int i = threadIdx.x >> 4, o = threadIdx.x & 15;
        sb2t[o * 20 + i] = b2g[threadIdx.x];
        sroot[threadIdx.x] = rootg[threadIdx.x];
    }
    if (threadIdx.x < 16) { sbias[threadIdx.x] = biasg[threadIdx.x];
                            bsum[threadIdx.x] = 0.f; bsq[threadIdx.x] = 0.f; }
    __syncthreads();

    const unsigned FULL = 0xffffffffu;
    int warp = threadIdx.x >> 5, lane = threadIdx.x & 31;
    int j = lane >> 1;                   // 0..15
    int ibase = (lane & 1) * 8;
    int o = lane & 15;
    int hf = lane >> 4;                  // contraction row-half
    float* ss = sS[warp];
    float lsum = 0.f, lsq = 0.f;

    for (int d0 = blockIdx.x * 16 + warp * 2; d0 < Nn; d0 += gridDim.x * 16) {
        int d1 = d0 + 1;
        // ---- edge loop node 0 ----
        int beg0 = g_eoff[d0], end0 = g_eoff[d0 + 1];
        float A0=0.f,A1=0.f,A2=0.f,A3=0.f,A4=0.f,A5=0.f,A6=0.f,A7=0.f,TA=0.f;
        for (int p = beg0; p < end0; p++) {
            int s = g_srcs[p];
            float a = (lane < 16) ? g_he[(size_t)p * 16 + lane]
                                  : g_h[s * 16 + (lane - 16)];
            float hej = __shfl_sync(FULL, a, j);
            TA += __shfl_sync(FULL, a, 16 + o);
            A0 = fmaf(hej, __shfl_sync(FULL, a, 16 + ibase + 0), A0);
            A1 = fmaf(hej, __shfl_sync(FULL, a, 16 + ibase + 1), A1);
            A2 = fmaf(hej, __shfl_sync(FULL, a, 16 + ibase + 2), A2);
            A3 = fmaf(hej, __shfl_sync(FULL, a, 16 + ibase + 3), A3);
            A4 = fmaf(hej, __shfl_sync(FULL, a, 16 + ibase + 4), A4);
            A5 = fmaf(hej, __shfl_sync(FULL, a, 16 + ibase + 5), A5);
            A6 = fmaf(hej, __shfl_sync(FULL, a, 16 + ibase + 6), A6);
            A7 = fmaf(hej, __shfl_sync(FULL, a, 16 + ibase + 7), A7);
        }
        // ---- edge loop node 1 ----
        float B0=0.f,B1=0.f,B2=0.f,B3=0.f,B4=0.f,B5=0.f,B6=0.f,B7=0.f,TB=0.f;
        int beg1 = 0, end1 = 0;
        if (d1 < Nn) {
            beg1 = g_eoff[d1]; end1 = g_eoff[d1 + 1];
            for (int p = beg1; p < end1; p++) {
                int s = g_srcs[p];
                float a = (lane < 16) ? g_he[(size_t)p * 16 + lane]
                                      : g_h[s * 16 + (lane - 16)];
                float hej = __shfl_sync(FULL, a, j);
                TB += __shfl_sync(FULL, a, 16 + o);
                B0 = fmaf(hej, __shfl_sync(FULL, a, 16 + ibase + 0), B0);
                B1 = fmaf(hej, __shfl_sync(FULL, a, 16 + ibase + 1), B1);
                B2 = fmaf(hej, __shfl_sync(FULL, a, 16 + ibase + 2), B2);
                B3 = fmaf(hej, __shfl_sync(FULL, a, 16 + ibase + 3), B3);
                B4 = fmaf(hej, __shfl_sync(FULL, a, 16 + ibase + 4), B4);
                B5 = fmaf(hej, __shfl_sync(FULL, a, 16 + ibase + 5), B5);
                B6 = fmaf(hej, __shfl_sync(FULL, a, 16 + ibase + 6), B6);
                B7 = fmaf(hej, __shfl_sync(FULL, a, 16 + ibase + 7), B7);
            }
        }
        // ---- stage both nodes' S,T ----
        int sb = j * 16 + ibase;
        *(float4*)&ss[sb]       = make_float4(A0, A1, A2, A3);
        *(float4*)&ss[sb + 4]   = make_float4(A4, A5, A6, A7);
        *(float4*)&ss[272 + sb]     = make_float4(B0, B1, B2, B3);
        *(float4*)&ss[272 + sb + 4] = make_float4(B4, B5, B6, B7);
        if (lane < 16) { ss[256 + lane] = TA; ss[272 + 256 + lane] = TB; }
        __syncwarp();

        // ---- contraction: one pass over w2t serves both nodes ----
        float acc_a = 0.f, acc_b = 0.f;
        const float* wrow = &sw2t[o * 264 + hf * 128];
        const float* sa = &ss[hf * 128];
        const float* sbp = &ss[272 + hf * 128];
#pragma unroll 8
        for (int k = 0; k < 128; k += 4) {
            float4 w  = *(const float4*)(wrow + k);
            float4 xa = *(const float4*)(sa + k);
            float4 xb = *(const float4*)(sbp + k);
            acc_a = fmaf(xa.x, w.x, acc_a); acc_a = fmaf(xa.y, w.y, acc_a);
            acc_a = fmaf(xa.z, w.z, acc_a); acc_a = fmaf(xa.w, w.w, acc_a);
            acc_b = fmaf(xb.x, w.x, acc_b); acc_b = fmaf(xb.y, w.y, acc_b);
            acc_b = fmaf(xb.z, w.z, acc_b); acc_b = fmaf(xb.w, w.w, acc_b);
        }
        {   // b2 @ T terms (i-half per hf)
            const float* brow = &sb2t[o * 20 + hf * 8];
            float4 b0 = *(const float4*)(brow);
            float4 b1 = *(const float4*)(brow + 4);
            float4 t0 = *(const float4*)&ss[256 + hf * 8];
            float4 t1 = *(const float4*)&ss[256 + hf * 8 + 4];
            float4 u0 = *(const float4*)&ss[272 + 256 + hf * 8];
            float4 u1 = *(const float4*)&ss[272 + 256 + hf * 8 + 4];
            acc_a = fmaf(t0.x, b0.x, acc_a); acc_a = fmaf(t0.y, b0.y, acc_a);
            acc_a = fmaf(t0.z, b0.z, acc_a); acc_a = fmaf(t0.w, b0.w, acc_a);
            acc_a = fmaf(t1.x, b1.x, acc_a); acc_a = fmaf(t1.y, b1.y, acc_a);
            acc_a = fmaf(t1.z, b1.z, acc_a); acc_a = fmaf(t1.w, b1.w, acc_a);
            acc_b = fmaf(u0.x, b0.x, acc_b); acc_b = fmaf(u0.y, b0.y, acc_b);
            acc_b = fmaf(u0.z, b0.z, acc_b); acc_b = fmaf(u0.w, b0.w, acc_b);
            acc_b = fmaf(u1.x, b1.x, acc_b); acc_b = fmaf(u1.y, b1.y, acc_b);
            acc_b = fmaf(u1.z, b1.z, acc_b); acc_b = fmaf(u1.w, b1.w, acc_b);
        }
        acc_a += __shfl_down_sync(FULL, acc_a, 16);
        acc_b += __shfl_down_sync(FULL, acc_b, 16);

        // root terms
        float hda = (lane < 16) ? g_h[(size_t)d0 * 16 + lane] : 0.f;
        float hdb = (lane < 16 && d1 < Nn) ? g_h[(size_t)d1 * 16 + lane] : 0.f;
        float ra = 0.f, rb = 0.f;
#pragma unroll
        for (int i = 0; i < 16; i++) {
            float wv = sroot[i * 16 + o];
            ra = fmaf(__shfl_sync(FULL, hda, i), wv, ra);
            rb = fmaf(__shfl_sync(FULL, hdb, i), wv, rb);
        }
        if (lane < 16) {
            float dega = fmaxf((float)(end0 - beg0), 1.0f);
            float resa = acc_a / dega + ra + sbias[o];
            g_h2[(size_t)d0 * 16 + o] = resa;
            lsum += resa; lsq = fmaf(resa, resa, lsq);
            if (d1 < Nn) {
                float degb = fmaxf((float)(end1 - beg1), 1.0f);
                float resb = acc_b / degb + rb + sbias[o];
                g_h2[(size_t)d1 * 16 + o] = resb;
                lsum += resb; lsq = fmaf(resb, resb, lsq);
            }
        }
        __syncwarp();
    }

    if (lane < 16) {
        atomicAdd(&bsum[o], lsum);
        atomicAdd(&bsq[o], lsq);
    }
    __syncthreads();
    if (threadIdx.x < 16) {
        atomicAdd(&g_stat3[layer * 32 + threadIdx.x], (double)bsum[threadIdx.x]);
        atomicAdd(&g_stat3[layer * 32 + 16 + threadIdx.x], (double)bsq[threadIdx.x]);
    }
}

// BN finalize inlined: every thread derives mu/rs from its layer's stat slot.
__global__ void k_apply(const float* __restrict__ gamma,
                        const float* __restrict__ beta,
                        float* __restrict__ hid_out, int layer) {
    int i = blockIdx.x * blockDim.x + threadIdx.x;
    if (i >= Nn * Dd) return;
    int c = i & 15;
    double mu = g_stat3[layer * 32 + c] / (double)Nn;
    double var = g_stat3[layer * 32 + 16 + c] / (double)Nn - mu * mu;
    if (var < 0.0) var = 0.0;
    float rs = rsqrtf((float)var + BN_EPS);
    float v = (g_h2[i] - (float)mu) * rs * __ldg(gamma + c) + __ldg(beta + c);
    v = ftanh(v);
    g_h[i] = v;
    if (hid_out) hid_out[i] = v;
}

// ---------------- fused readout: offsets + pooling + MLP head ----------------
__global__ void k_readout(const int* __restrict__ lengths,
                          const float* __restrict__ fc1w, const float* __restrict__ fc1b,
                          const float* __restrict__ fc2w, const float* __restrict__ fc2b,
                          float* __restrict__ pooled_out,
                          float* __restrict__ fc_out, float* __restrict__ lsm_out) {
    int g = blockIdx.x;
    __shared__ int ired[128];
    __shared__ float rsum[8][17], rmx[8][17], rmn[8][17];
    __shared__ float spool[64];
    __shared__ float sf1[16];
    __shared__ float sfc[10];

    // beg = sum lengths[0..g)
    int part = 0;
    for (int t = threadIdx.x; t < g; t += 128) part += lengths[t];
    ired[threadIdx.x] = part; __syncthreads();
    for (int s = 64; s > 0; s >>= 1) {
        if (threadIdx.x < s) ired[threadIdx.x] += ired[threadIdx.x + s];
        __syncthreads();
    }
    int beg = ired[0];
    int len = lengths[g];
    if (beg > Nn) beg = Nn;
    int end = beg + len; if (end > Nn) end = Nn;

    int c = threadIdx.x & 15, sub = threadIdx.x >> 4;
    float s = 0.f, mx = -INFINITY, mn = INFINITY;
    for (int n = beg + sub; n < end; n += 8) {
        float v = g_h[n * 16 + c];
        s += v; mx = fmaxf(mx, v); mn = fminf(mn, v);
    }
    rsum[sub][c] = s; rmx[sub][c] = mx; rmn[sub][c] = mn;
    __syncthreads();
    if (threadIdx.x < 16) {
        int cc = threadIdx.x;
        float S = 0.f, MX = -INFINITY, MN = INFINITY;
#pragma unroll
        for (int k = 0; k < 8; k++) {
            S += rsum[k][cc];
            MX = fmaxf(MX, rmx[k][cc]);
            MN = fminf(MN, rmn[k][cc]);
        }
        float cnt = fmaxf((float)len, 1.0f);
        spool[cc]      = S / cnt;
        spool[16 + cc] = MX;
        spool[32 + cc] = MN;
        spool[48 + cc] = S;
        pooled_out[g * 64 + cc]      = S / cnt;
        pooled_out[g * 64 + 16 + cc] = MX;
        pooled_out[g * 64 + 32 + cc] = MN;
        pooled_out[g * 64 + 48 + cc] = S;
    }
    __syncthreads();
    if (threadIdx.x < 16) {
        int cc = threadIdx.x;
        float acc = __ldg(fc1b + cc);
#pragma unroll
        for (int i = 0; i < 64; i++)
            acc = fmaf(spool[i], __ldg(fc1w + i * 16 + cc), acc);
        sf1[cc] = ftanh(acc);
    }
    __syncthreads();
    if (threadIdx.x < 10) {
        int cc = threadIdx.x;
        float acc = __ldg(fc2b + cc);
#pragma unroll
        for (int i = 0; i < 16; i++)
            acc = fmaf(sf1[i], __ldg(fc2w + i * 10 + cc), acc);
        sfc[cc] = acc;
        fc_out[g * 10 + cc] = acc;
    }
    __syncthreads();
    if (threadIdx.x < 10) {
        float m = -INFINITY;
#pragma unroll
        for (int k = 0; k < 10; k++) m = fmaxf(m, sfc[k]);
        float sum = 0.f;
#pragma unroll
        for (int k = 0; k < 10; k++) sum += __expf(sfc[k] - m);
        lsm_out[g * 10 + threadIdx.x] = sfc[threadIdx.x] - (m + __logf(sum));
    }
}

// ---------------- launch ----------------
extern "C" void kernel_launch(void* const* d_in, const int* in_sizes, int n_in,
                              void* d_out, int out_size) {
    const float* x         = (const float*)d_in[0];
    const float* edge_attr = (const float*)d_in[1];
    const float* edge_w1   = (const float*)d_in[2];
    const float* edge_b1   = (const float*)d_in[3];
    const float* edge_w2   = (const float*)d_in[4];
    const float* edge_b2   = (const float*)d_in[5];
    const float* root      = (const float*)d_in[6];
    const float* conv_bias = (const float*)d_in[7];
    const float* bn_gamma  = (const float*)d_in[8];
    const float* bn_beta   = (const float*)d_in[9];
    const float* fc1_w     = (const float*)d_in[10];
    const float* fc1_b     = (const float*)d_in[11];
    const float* fc2_w     = (const float*)d_in[12];
    const float* fc2_b     = (const float*)d_in[13];
    const int*   edge_index= (const int*)d_in[14];
    const int*   lengths   = (const int*)d_in[15];
    const int* src = edge_index;
    const int* dst = edge_index + Ee;
    float* out = (float*)d_out;

    // output layout resolution: tuple concat [hidden, pooled, fc, log_softmax]
    const int FULL = Nn * Dd + Gg * 4 * Dd + Gg * Cc + Gg * Cc;  // 842000
    float *hid_dst = nullptr, *pool_dst, *fc_dst, *lsm_dst;
    void *p_pool = nullptr, *p_fc = nullptr;
    cudaGetSymbolAddress(&p_pool, g_pooled);
    cudaGetSymbolAddress(&p_fc, g_fcbuf);
    pool_dst = (float*)p_pool; fc_dst = (float*)p_fc; lsm_dst = (float*)p_fc;
    if (out_size >= FULL) {
        hid_dst  = out;
        pool_dst = out + Nn * Dd;
        fc_dst   = pool_dst + Gg * 4 * Dd;
        lsm_dst  = fc_dst + Gg * Cc;
    } else if (out_size == Gg * Cc) {
        lsm_dst = out;
    } else if (out_size == 2 * Gg * Cc) {
        fc_dst = out; lsm_dst = out + Gg * Cc;
    } else if (out_size == Nn * Dd) {
        hid_dst = out;
    }

    const int B = 256;
    k_setup<<<(Nn * Dd + B - 1) / B, B>>>(x);
    k_hist<<<(Ee + B - 1) / B, B>>>(dst);
    k_scanA<<<NBS, 256>>>();
    k_scanB<<<1, 256>>>();
    k_scanC<<<(Nn + B - 1) / B, B>>>();
    k_scatter_mlp<<<(Ee + 127) / 128, 128>>>(src, dst, edge_attr, edge_w1, edge_b1);

    for (int l = 0; l < 3; l++) {
        k_conv<<<592, 256>>>(edge_w2, edge_b2, root + l * Dd * Dd, conv_bias + l * Dd, l);
        k_apply<<<(Nn * Dd + B - 1) / B, B>>>(bn_gamma + l * Dd, bn_beta + l * Dd,
                                              (l == 2) ? hid_dst : nullptr, l);
    }

    k_readout<<<Gg, 128>>>(lengths, fc1_w, fc1_b, fc2_w, fc2_b,
                           pool_dst, fc_dst, lsm_dst);
}

// round 17
// speedup vs baseline: 1.0019x; 1.0019x over previous
#include <cuda_runtime.h>
#include <math.h>

#define Nn 50000
#define Ee 500000
#define Dd 16
#define EFf 8
#define Cc 10
#define Gg 500
#define BN_EPS 1e-5f
#define NBS 196   // ceil(Nn/256)

// ---------------- device scratch (static, allocation-free) ----------------
__device__ float  g_he[(size_t)Ee * Dd];     // per-edge MLP hidden, dst-sorted order
__device__ float  g_h[Nn * Dd];              // current node features
__device__ float  g_h2[Nn * Dd];             // pre-BN features
__device__ int    g_cnt[Nn];                 // histogram
__device__ int    g_rank[Ee];                // per-edge rank within its dst bucket
__device__ int    g_eoff[Nn + 1];            // CSR offsets (edges sorted by dst)
__device__ int    g_bsum[256];               // scan block sums
__device__ int    g_srcs[Ee];                // src id, dst-sorted order
__device__ double g_stat3[3 * 32];           // per-layer BN sum/sumsq slots
__device__ float  g_pooled[Gg * 4 * Dd];     // pooled scratch (fallback path)
__device__ float  g_fcbuf[Gg * Cc];          // fc scratch (fallback path)

// fast tanh: 1 - 2/(e^{2x}+1); exact at +/-inf, ~1e-6 rel err
__device__ __forceinline__ float ftanh(float x) {
    float e = __expf(2.0f * x);
    return 1.0f - __fdividef(2.0f, e + 1.0f);
}

// ---------------- setup kernels ----------------

__global__ void k_setup(const float* __restrict__ x) {
    int i = blockIdx.x * blockDim.x + threadIdx.x;
    if (i < Nn * Dd) g_h[i] = x[i];
    if (i < Nn) g_cnt[i] = 0;
    if (i < 3 * 32) g_stat3[i] = 0.0;
}

__global__ void k_hist(const int* __restrict__ dst) {
    int e = blockIdx.x * blockDim.x + threadIdx.x;
    if (e < Ee) g_rank[e] = atomicAdd(&g_cnt[dst[e]], 1);
}

__global__ void k_scanA() {
    __shared__ int sh[256];
    int t = threadIdx.x;
    int i = blockIdx.x * 256 + t;
    int v = (i < Nn) ? g_cnt[i] : 0;
    sh[t] = v; __syncthreads();
    for (int ofs = 1; ofs < 256; ofs <<= 1) {
        int add = (t >= ofs) ? sh[t - ofs] : 0;
        __syncthreads();
        sh[t] += add;
        __syncthreads();
    }
    if (i < Nn) g_eoff[i] = sh[t] - v;         // exclusive
    if (t == 255) g_bsum[blockIdx.x] = sh[255];
}

__global__ void k_scanB() {
    __shared__ int sh[256];
    int t = threadIdx.x;
    int v = (t < NBS) ? g_bsum[t] : 0;
    sh[t] = v; __syncthreads();
    for (int ofs = 1; ofs < 256; ofs <<= 1) {
        int add = (t >= ofs) ? sh[t - ofs] : 0;
        __syncthreads();
        sh[t] += add;
        __syncthreads();
    }
    if (t < NBS) g_bsum[t] = sh[t] - v;        // exclusive
}

__global__ void k_scanC() {
    int i = blockIdx.x * blockDim.x + threadIdx.x;
    if (i < Nn) g_eoff[i] += g_bsum[i >> 8];
    if (i == 0) g_eoff[Nn] = Ee;
}

// fused: scatter src into sorted order + compute edge MLP row directly into
// the sorted slot. edge_attr read COALESCED (thread e = edge e).
__global__ void k_scatter_mlp(const int* __restrict__ src, const int* __restrict__ dst,
                              const float* __restrict__ ea,
                              const float* __restrict__ w1, const float* __restrict__ b1) {
    __shared__ float sw1t[16][8];   // [c][f]
    __shared__ float sb1[16];
    if (threadIdx.x < 128) {
        int f = threadIdx.x >> 4, c = threadIdx.x & 15;
        sw1t[c][f] = w1[threadIdx.x];
    }
    if (threadIdx.x < 16) sb1[threadIdx.x] = b1[threadIdx.x];
    __syncthreads();
    int e = blockIdx.x * blockDim.x + threadIdx.x;
    if (e >= Ee) return;
    int d = dst[e];
    int pos = g_eoff[d] + g_rank[e];
    g_srcs[pos] = src[e];
    float4 a0 = *(const float4*)(ea + (size_t)e * 8);
    float4 a1 = *(const float4*)(ea + (size_t)e * 8 + 4);
    float hv[16];
#pragma unroll
    for (int c = 0; c < 16; c++) {
        const float* wc = sw1t[c];
        float acc = sb1[c];
        acc = fmaf(a0.x, wc[0], acc); acc = fmaf(a0.y, wc[1], acc);
        acc = fmaf(a0.z, wc[2], acc); acc = fmaf(a0.w, wc[3], acc);
        acc = fmaf(a1.x, wc[4], acc); acc = fmaf(a1.y, wc[5], acc);
        acc = fmaf(a1.z, wc[6], acc); acc = fmaf(a1.w, wc[7], acc);
        hv[c] = ftanh(acc);
    }
    float4* hp = (float4*)(g_he + (size_t)pos * 16);
    hp[0] = make_float4(hv[0],  hv[1],  hv[2],  hv[3]);
    hp[1] = make_float4(hv[4],  hv[5],  hv[6],  hv[7]);
    hp[2] = make_float4(hv[8],  hv[9],  hv[10], hv[11]);
    hp[3] = make_float4(hv[12], hv[13], hv[14], hv[15]);
}

// ---------------- fused NNConv layer: 2 nodes per warp ----------------
// S[j,i] = sum_e he[e,j]*h[src,i], T[i] = sum_e h[src,i]; contraction against
// transposed+padded w2t[o][row] amortized across the node pair.
__global__ void k_conv(const float* __restrict__ w2g, const float* __restrict__ b2g,
                       const float* __restrict__ rootg, const float* __restrict__ biasg,
                       int layer) {
    __shared__ float sw2t[16 * 264];     // [o][row=j*16+i], pitch 264
    __shared__ float sb2t[16 * 20];      // [o][i], pitch 20
    __shared__ float sroot[256];         // [i*16+o]
    __shared__ float sbias[16];
    __shared__ float sS[8][544];         // per warp: node0 S[256]+T[16], node1 at +272
    __shared__ float bsum[16], bsq[16];

    for (int t = threadIdx.x; t < 4096; t += 256) {
        int row = t >> 4, o = t & 15;
        sw2t[o * 264 + row] = w2g[t];
    }
    if (threadIdx.x < 256) {
        int i = threadIdx.x >> 4, o = threadIdx.x & 15;
        sb2t[o * 20 + i] = b2g[threadIdx.x];
        sroot[threadIdx.x] = rootg[threadIdx.x];
    }
    if (threadIdx.x < 16) { sbias[threadIdx.x] = biasg[threadIdx.x];
                            bsum[threadIdx.x] = 0.f; bsq[threadIdx.x] = 0.f; }
    __syncthreads();

    const unsigned FULL = 0xffffffffu;
    int warp = threadIdx.x >> 5, lane = threadIdx.x & 31;
    int j = lane >> 1;                   // 0..15
    int ibase = (lane & 1) * 8;
    int o = lane & 15;
    int hf = lane >> 4;                  // contraction row-half
    float* ss = sS[warp];
    float lsum = 0.f, lsq = 0.f;

    for (int d0 = blockIdx.x * 16 + warp * 2; d0 < Nn; d0 += gridDim.x * 16) {
        int d1 = d0 + 1;
        // ---- edge loop node 0 ----
        int beg0 = g_eoff[d0], end0 = g_eoff[d0 + 1];
        float A0=0.f,A1=0.f,A2=0.f,A3=0.f,A4=0.f,A5=0.f,A6=0.f,A7=0.f,TA=0.f;
        for (int p = beg0; p < end0; p++) {
            int s = g_srcs[p];
            float a = (lane < 16) ? g_he[(size_t)p * 16 + lane]
                                  : g_h[s * 16 + (lane - 16)];
            float hej = __shfl_sync(FULL, a, j);
            TA += __shfl_sync(FULL, a, 16 + o);
            A0 = fmaf(hej, __shfl_sync(FULL, a, 16 + ibase + 0), A0);
            A1 = fmaf(hej, __shfl_sync(FULL, a, 16 + ibase + 1), A1);
            A2 = fmaf(hej, __shfl_sync(FULL, a, 16 + ibase + 2), A2);
            A3 = fmaf(hej, __shfl_sync(FULL, a, 16 + ibase + 3), A3);
            A4 = fmaf(hej, __shfl_sync(FULL, a, 16 + ibase + 4), A4);
            A5 = fmaf(hej, __shfl_sync(FULL, a, 16 + ibase + 5), A5);
            A6 = fmaf(hej, __shfl_sync(FULL, a, 16 + ibase + 6), A6);
            A7 = fmaf(hej, __shfl_sync(FULL, a, 16 + ibase + 7), A7);
        }
        // ---- edge loop node 1 ----
        float B0=0.f,B1=0.f,B2=0.f,B3=0.f,B4=0.f,B5=0.f,B6=0.f,B7=0.f,TB=0.f;
        int beg1 = 0, end1 = 0;
        if (d1 < Nn) {
            beg1 = g_eoff[d1]; end1 = g_eoff[d1 + 1];
            for (int p = beg1; p < end1; p++) {
                int s = g_srcs[p];
                float a = (lane < 16) ? g_he[(size_t)p * 16 + lane]
                                      : g_h[s * 16 + (lane - 16)];
                float hej = __shfl_sync(FULL, a, j);
                TB += __shfl_sync(FULL, a, 16 + o);
                B0 = fmaf(hej, __shfl_sync(FULL, a, 16 + ibase + 0), B0);
                B1 = fmaf(hej, __shfl_sync(FULL, a, 16 + ibase + 1), B1);
                B2 = fmaf(hej, __shfl_sync(FULL, a, 16 + ibase + 2), B2);
                B3 = fmaf(hej, __shfl_sync(FULL, a, 16 + ibase + 3), B3);
                B4 = fmaf(hej, __shfl_sync(FULL, a, 16 + ibase + 4), B4);
                B5 = fmaf(hej, __shfl_sync(FULL, a, 16 + ibase + 5), B5);
                B6 = fmaf(hej, __shfl_sync(FULL, a, 16 + ibase + 6), B6);
                B7 = fmaf(hej, __shfl_sync(FULL, a, 16 + ibase + 7), B7);
            }
        }
        // ---- stage both nodes' S,T ----
        int sb = j * 16 + ibase;
        *(float4*)&ss[sb]       = make_float4(A0, A1, A2, A3);
        *(float4*)&ss[sb + 4]   = make_float4(A4, A5, A6, A7);
        *(float4*)&ss[272 + sb]     = make_float4(B0, B1, B2, B3);
        *(float4*)&ss[272 + sb + 4] = make_float4(B4, B5, B6, B7);
        if (lane < 16) { ss[256 + lane] = TA; ss[272 + 256 + lane] = TB; }
        __syncwarp();

        // ---- contraction: one pass over w2t serves both nodes ----
        float acc_a = 0.f, acc_b = 0.f;
        const float* wrow = &sw2t[o * 264 + hf * 128];
        const float* sa = &ss[hf * 128];
        const float* sbp = &ss[272 + hf * 128];
#pragma unroll 8
        for (int k = 0; k < 128; k += 4) {
            float4 w  = *(const float4*)(wrow + k);
            float4 xa = *(const float4*)(sa + k);
            float4 xb = *(const float4*)(sbp + k);
            acc_a = fmaf(xa.x, w.x, acc_a); acc_a = fmaf(xa.y, w.y, acc_a);
            acc_a = fmaf(xa.z, w.z, acc_a); acc_a = fmaf(xa.w, w.w, acc_a);
            acc_b = fmaf(xb.x, w.x, acc_b); acc_b = fmaf(xb.y, w.y, acc_b);
            acc_b = fmaf(xb.z, w.z, acc_b); acc_b = fmaf(xb.w, w.w, acc_b);
        }
        {   // b2 @ T terms (i-half per hf)
            const float* brow = &sb2t[o * 20 + hf * 8];
            float4 b0 = *(const float4*)(brow);
            float4 b1 = *(const float4*)(brow + 4);
            float4 t0 = *(const float4*)&ss[256 + hf * 8];
            float4 t1 = *(const float4*)&ss[256 + hf * 8 + 4];
            float4 u0 = *(const float4*)&ss[272 + 256 + hf * 8];
            float4 u1 = *(const float4*)&ss[272 + 256 + hf * 8 + 4];
            acc_a = fmaf(t0.x, b0.x, acc_a); acc_a = fmaf(t0.y, b0.y, acc_a);
            acc_a = fmaf(t0.z, b0.z, acc_a); acc_a = fmaf(t0.w, b0.w, acc_a);
            acc_a = fmaf(t1.x, b1.x, acc_a); acc_a = fmaf(t1.y, b1.y, acc_a);
            acc_a = fmaf(t1.z, b1.z, acc_a); acc_a = fmaf(t1.w, b1.w, acc_a);
            acc_b = fmaf(u0.x, b0.x, acc_b); acc_b = fmaf(u0.y, b0.y, acc_b);
            acc_b = fmaf(u0.z, b0.z, acc_b); acc_b = fmaf(u0.w, b0.w, acc_b);
            acc_b = fmaf(u1.x, b1.x, acc_b); acc_b = fmaf(u1.y, b1.y, acc_b);
            acc_b = fmaf(u1.z, b1.z, acc_b); acc_b = fmaf(u1.w, b1.w, acc_b);
        }
        acc_a += __shfl_down_sync(FULL, acc_a, 16);
        acc_b += __shfl_down_sync(FULL, acc_b, 16);

        // root terms
        float hda = (lane < 16) ? g_h[(size_t)d0 * 16 + lane] : 0.f;
        float hdb = (lane < 16 && d1 < Nn) ? g_h[(size_t)d1 * 16 + lane] : 0.f;
        float ra = 0.f, rb = 0.f;
#pragma unroll
        for (int i = 0; i < 16; i++) {
            float wv = sroot[i * 16 + o];
            ra = fmaf(__shfl_sync(FULL, hda, i), wv, ra);
            rb = fmaf(__shfl_sync(FULL, hdb, i), wv, rb);
        }
        if (lane < 16) {
            float dega = fmaxf((float)(end0 - beg0), 1.0f);
            float resa = acc_a / dega + ra + sbias[o];
            g_h2[(size_t)d0 * 16 + o] = resa;
            lsum += resa; lsq = fmaf(resa, resa, lsq);
            if (d1 < Nn) {
                float degb = fmaxf((float)(end1 - beg1), 1.0f);
                float resb = acc_b / degb + rb + sbias[o];
                g_h2[(size_t)d1 * 16 + o] = resb;
                lsum += resb; lsq = fmaf(resb, resb, lsq);
            }
        }
        __syncwarp();
    }

    if (lane < 16) {
        atomicAdd(&bsum[o], lsum);
        atomicAdd(&bsq[o], lsq);
    }
    __syncthreads();
    if (threadIdx.x < 16) {
        atomicAdd(&g_stat3[layer * 32 + threadIdx.x], (double)bsum[threadIdx.x]);
        atomicAdd(&g_stat3[layer * 32 + 16 + threadIdx.x], (double)bsq[threadIdx.x]);
    }
}

// BN finalize inlined: every thread derives mu/rs from its layer's stat slot.
__global__ void k_apply(const float* __restrict__ gamma,
                        const float* __restrict__ beta,
                        float* __restrict__ hid_out, int layer) {
    int i = blockIdx.x * blockDim.x + threadIdx.x;
    if (i >= Nn * Dd) return;
    int c = i & 15;
    double mu = g_stat3[layer * 32 + c] / (double)Nn;
    double var = g_stat3[layer * 32 + 16 + c] / (double)Nn - mu * mu;
    if (var < 0.0) var = 0.0;
    float rs = rsqrtf((float)var + BN_EPS);
    float v = (g_h2[i] - (float)mu) * rs * __ldg(gamma + c) + __ldg(beta + c);
    v = ftanh(v);
    g_h[i] = v;
    if (hid_out) hid_out[i] = v;
}

// ---------------- fused readout: offsets + pooling + MLP head ----------------
__global__ void k_readout(const int* __restrict__ lengths,
                          const float* __restrict__ fc1w, const float* __restrict__ fc1b,
                          const float* __restrict__ fc2w, const float* __restrict__ fc2b,
                          float* __restrict__ pooled_out,
                          float* __restrict__ fc_out, float* __restrict__ lsm_out) {
    int g = blockIdx.x;
    __shared__ int ired[128];
    __shared__ float rsum[8][17], rmx[8][17], rmn[8][17];
    __shared__ float spool[64];
    __shared__ float sf1[16];
    __shared__ float sfc[10];

    // beg = sum lengths[0..g)
    int part = 0;
    for (int t = threadIdx.x; t < g; t += 128) part += lengths[t];
    ired[threadIdx.x] = part; __syncthreads();
    for (int s = 64; s > 0; s >>= 1) {
        if (threadIdx.x < s) ired[threadIdx.x] += ired[threadIdx.x + s];
        __syncthreads();
    }
    int beg = ired[0];
    int len = lengths[g];
    if (beg > Nn) beg = Nn;
    int end = beg + len; if (end > Nn) end = Nn;

    int c = threadIdx.x & 15, sub = threadIdx.x >> 4;
    float s = 0.f, mx = -INFINITY, mn = INFINITY;
    for (int n = beg + sub; n < end; n += 8) {
        float v = g_h[n * 16 + c];
        s += v; mx = fmaxf(mx, v); mn = fminf(mn, v);
    }
    rsum[sub][c] = s; rmx[sub][c] = mx; rmn[sub][c] = mn;
    __syncthreads();
    if (threadIdx.x < 16) {
        int cc = threadIdx.x;
        float S = 0.f, MX = -INFINITY, MN = INFINITY;
#pragma unroll
        for (int k = 0; k < 8; k++) {
            S += rsum[k][cc];
            MX = fmaxf(MX, rmx[k][cc]);
            MN = fminf(MN, rmn[k][cc]);
        }
        float cnt = fmaxf((float)len, 1.0f);
        spool[cc]      = S / cnt;
        spool[16 + cc] = MX;
        spool[32 + cc] = MN;
        spool[48 + cc] = S;
        pooled_out[g * 64 + cc]      = S / cnt;
        pooled_out[g * 64 + 16 + cc] = MX;
        pooled_out[g * 64 + 32 + cc] = MN;
        pooled_out[g * 64 + 48 + cc] = S;
    }
    __syncthreads();
    if (threadIdx.x < 16) {
        int cc = threadIdx.x;
        float acc = __ldg(fc1b + cc);
#pragma unroll
        for (int i = 0; i < 64; i++)
            acc = fmaf(spool[i], __ldg(fc1w + i * 16 + cc), acc);
        sf1[cc] = ftanh(acc);
    }
    __syncthreads();
    if (threadIdx.x < 10) {
        int cc = threadIdx.x;
        float acc = __ldg(fc2b + cc);
#pragma unroll
        for (int i = 0; i < 16; i++)
            acc = fmaf(sf1[i], __ldg(fc2w + i * 10 + cc), acc);
        sfc[cc] = acc;
        fc_out[g * 10 + cc] = acc;
    }
    __syncthreads();
    if (threadIdx.x < 10) {
        float m = -INFINITY;
#pragma unroll
        for (int k = 0; k < 10; k++) m = fmaxf(m, sfc[k]);
        float sum = 0.f;
#pragma unroll
        for (int k = 0; k < 10; k++) sum += __expf(sfc[k] - m);
        lsm_out[g * 10 + threadIdx.x] = sfc[threadIdx.x] - (m + __logf(sum));
    }
}

// ---------------- launch ----------------
extern "C" void kernel_launch(void* const* d_in, const int* in_sizes, int n_in,
                              void* d_out, int out_size) {
    const float* x         = (const float*)d_in[0];
    const float* edge_attr = (const float*)d_in[1];
    const float* edge_w1   = (const float*)d_in[2];
    const float* edge_b1   = (const float*)d_in[3];
    const float* edge_w2   = (const float*)d_in[4];
    const float* edge_b2   = (const float*)d_in[5];
    const float* root      = (const float*)d_in[6];
    const float* conv_bias = (const float*)d_in[7];
    const float* bn_gamma  = (const float*)d_in[8];
    const float* bn_beta   = (const float*)d_in[9];
    const float* fc1_w     = (const float*)d_in[10];
    const float* fc1_b     = (const float*)d_in[11];
    const float* fc2_w     = (const float*)d_in[12];
    const float* fc2_b     = (const float*)d_in[13];
    const int*   edge_index= (const int*)d_in[14];
    const int*   lengths   = (const int*)d_in[15];
    const int* src = edge_index;
    const int* dst = edge_index + Ee;
    float* out = (float*)d_out;

    // output layout resolution: tuple concat [hidden, pooled, fc, log_softmax]
    const int FULL = Nn * Dd + Gg * 4 * Dd + Gg * Cc + Gg * Cc;  // 842000
    float *hid_dst = nullptr, *pool_dst, *fc_dst, *lsm_dst;
    void *p_pool = nullptr, *p_fc = nullptr;
    cudaGetSymbolAddress(&p_pool, g_pooled);
    cudaGetSymbolAddress(&p_fc, g_fcbuf);
    pool_dst = (float*)p_pool; fc_dst = (float*)p_fc; lsm_dst = (float*)p_fc;
    if (out_size >= FULL) {
        hid_dst  = out;
        pool_dst = out + Nn * Dd;
        fc_dst   = pool_dst + Gg * 4 * Dd;
        lsm_dst  = fc_dst + Gg * Cc;
    } else if (out_size == Gg * Cc) {
        lsm_dst = out;
    } else if (out_size == 2 * Gg * Cc) {
        fc_dst = out; lsm_dst = out + Gg * Cc;
    } else if (out_size == Nn * Dd) {
        hid_dst = out;
    }

    const int B = 256;
    k_setup<<<(Nn * Dd + B - 1) / B, B>>>(x);
    k_hist<<<(Ee + B - 1) / B, B>>>(dst);
    k_scanA<<<NBS, 256>>>();
    k_scanB<<<1, 256>>>();
    k_scanC<<<(Nn + B - 1) / B, B>>>();
    k_scatter_mlp<<<(Ee + 127) / 128, 128>>>(src, dst, edge_attr, edge_w1, edge_b1);

    for (int l = 0; l < 3; l++) {
        k_conv<<<592, 256>>>(edge_w2, edge_b2, root + l * Dd * Dd, conv_bias + l * Dd, l);
        k_apply<<<(Nn * Dd + B - 1) / B, B>>>(bn_gamma + l * Dd, bn_beta + l * Dd,
                                              (l == 2) ? hid_dst : nullptr, l);
    }

    k_readout<<<Gg, 128>>>(lengths, fc1_w, fc1_b, fc2_w, fc2_b,
                           pool_dst, fc_dst, lsm_dst);
}